// round 8
// baseline (speedup 1.0000x reference)
#include <cuda_runtime.h>
#include <cstdint>

#define B_  32
#define T_  2048
#define IN_ 512
#define H_  256
#define NG  32      // groups of 8 presynaptic neurons
#define NP  256     // patterns per group (2^8)
#define NCH 32      // T_/64 proj chunks per batch

#define NSCAN 16    // scan CTAs (two batches each)
#define NWORK 64    // persistent GEMM worker CTAs
#define NJOBS 2048  // (B_*T_/GM) * 2 n-halves

// Scratch (allocation-free rule: __device__ globals)
__device__ float g_proj[(size_t)B_ * T_ * H_];        // 64 MB input projection
__device__ float g_Vt[H_ * H_];                       // Vt[j][h] = V[h][j]
__device__ float g_tab[(size_t)NG * NP * H_];         // 8 MB group subset-sum table
__device__ unsigned g_flag[B_ * NCH];                 // producer->consumer chunk flags

// ---------------------------------------------------------------------------
// Setup kernels
// ---------------------------------------------------------------------------
__global__ void transpose_V(const float* __restrict__ V) {
    int j = blockIdx.x;
    int h = threadIdx.x;
    g_Vt[j * H_ + h] = V[h * H_ + j];
}

// tab[g][p][h] = sum_{i: bit i of p} Vt[8g+i][h]   (ascending i)
__global__ void build_tab(void) {
    const int blk = blockIdx.x;          // 0..8191
    const int g = blk >> 8;
    const int p = blk & 255;
    const int h = threadIdx.x;
    float s = 0.0f;
    #pragma unroll
    for (int i = 0; i < 8; i++)
        if ((p >> i) & 1)
            s = __fadd_rn(s, g_Vt[(g * 8 + i) * H_ + h]);
    g_tab[((size_t)g * NP + p) * H_ + h] = s;
}

__global__ void init_flags(void) {
    g_flag[threadIdx.x] = 0u;
}

// ---------------------------------------------------------------------------
// chunk-ready spin (acquire)
// ---------------------------------------------------------------------------
__device__ __forceinline__ void wait_chunk(const unsigned* f) {
    unsigned v;
    do {
        asm volatile("ld.acquire.gpu.global.u32 %0, [%1];"
                     : "=r"(v) : "l"(f) : "memory");
    } while (v < 2u);
}

// gather 8 pattern-indexed table rows (ascending group order), skipping
// all-zero patterns (their rows are exactly +0.0 -> adds are no-ops)
__device__ __forceinline__ float4 gather8(const char* tbase, unsigned wA, unsigned wB) {
    float4 acc = make_float4(0.f, 0.f, 0.f, 0.f);
    #pragma unroll
    for (int i = 0; i < 8; i++) {
        unsigned pat = (i < 4) ? ((wA >> (8 * i)) & 0xFFu)
                               : ((wB >> (8 * (i - 4))) & 0xFFu);
        if (pat) {
            const float4 v = *(const float4*)(tbase + (((unsigned)i << 8) + pat) * 1024u);
            acc.x = __fadd_rn(acc.x, v.x);
            acc.y = __fadd_rn(acc.y, v.y);
            acc.z = __fadd_rn(acc.z, v.z);
            acc.w = __fadd_rn(acc.w, v.w);
        }
    }
    return acc;
}

// ---------------------------------------------------------------------------
// Fused persistent kernel.
//   CTA 0..15  : LIF scan for batches (cta, cta+16), interleaved
//   CTA 16..79 : GEMM workers, grid-stride over NJOBS tile jobs
// ---------------------------------------------------------------------------
#define GM 64
#define GN 128
#define GK 16

__global__ __launch_bounds__(256, 1) void fused_kernel(
    const float* __restrict__ x, const float* __restrict__ W,
    const float* __restrict__ bia,
    const float* __restrict__ b_rec, float* __restrict__ out) {

    __shared__ float As[2][GK][GM];        // GEMM buffers (worker role)
    __shared__ float Bs[2][GK][GN];
    __shared__ float4 sp[2][2][4][64];     // [buf][batchAB][quarter][u]
    __shared__ unsigned sbits[2][2][8];    // [buf][batchAB][warp]

    const int cta = blockIdx.x;
    const int tid = threadIdx.x;

    if (cta >= NSCAN) {
        // =================== GEMM worker role ===================
        const int tx = tid & 15;
        const int ty = tid >> 4;
        const int lr = tid >> 2;
        const int lc = (tid & 3) * 4;

        for (int jj = cta - NSCAN; jj < NJOBS; jj += NWORK) {
            const int nt = jj & 1;
            const int b  = (jj >> 1) & 31;
            const int tc = jj >> 6;
            const size_t m0 = (size_t)b * T_ + (size_t)tc * GM;
            const int bn = nt * GN;

            float acc[4][8];
            #pragma unroll
            for (int i = 0; i < 4; i++)
                #pragma unroll
                for (int j = 0; j < 8; j++) acc[i][j] = 0.0f;

            float4 ra, rb0, rb1;
            ra  = *(const float4*)&x[(m0 + lr) * IN_ + lc];
            rb0 = *(const float4*)&W[(size_t)(bn + lr) * IN_ + lc];
            rb1 = *(const float4*)&W[(size_t)(bn + 64 + lr) * IN_ + lc];
            As[0][lc + 0][lr] = ra.x;  As[0][lc + 1][lr] = ra.y;
            As[0][lc + 2][lr] = ra.z;  As[0][lc + 3][lr] = ra.w;
            Bs[0][lc + 0][lr] = rb0.x; Bs[0][lc + 1][lr] = rb0.y;
            Bs[0][lc + 2][lr] = rb0.z; Bs[0][lc + 3][lr] = rb0.w;
            Bs[0][lc + 0][lr + 64] = rb1.x; Bs[0][lc + 1][lr + 64] = rb1.y;
            Bs[0][lc + 2][lr + 64] = rb1.z; Bs[0][lc + 3][lr + 64] = rb1.w;
            __syncthreads();

            const int NT = IN_ / GK;   // 32
            for (int kt = 0; kt < NT; kt++) {
                const int cur = kt & 1, nxt = cur ^ 1;
                if (kt + 1 < NT) {
                    int k0 = (kt + 1) * GK + lc;
                    ra  = *(const float4*)&x[(m0 + lr) * IN_ + k0];
                    rb0 = *(const float4*)&W[(size_t)(bn + lr) * IN_ + k0];
                    rb1 = *(const float4*)&W[(size_t)(bn + 64 + lr) * IN_ + k0];
                }
                #pragma unroll
                for (int kk = 0; kk < GK; kk++) {
                    float a[4], bb[8];
                    *(float4*)&a[0]  = *(const float4*)&As[cur][kk][ty * 4];
                    *(float4*)&bb[0] = *(const float4*)&Bs[cur][kk][tx * 8];
                    *(float4*)&bb[4] = *(const float4*)&Bs[cur][kk][tx * 8 + 4];
                    #pragma unroll
                    for (int i = 0; i < 4; i++)
                        #pragma unroll
                        for (int j = 0; j < 8; j++)
                            acc[i][j] = fmaf(a[i], bb[j], acc[i][j]);
                }
                if (kt + 1 < NT) {
                    As[nxt][lc + 0][lr] = ra.x;  As[nxt][lc + 1][lr] = ra.y;
                    As[nxt][lc + 2][lr] = ra.z;  As[nxt][lc + 3][lr] = ra.w;
                    Bs[nxt][lc + 0][lr] = rb0.x; Bs[nxt][lc + 1][lr] = rb0.y;
                    Bs[nxt][lc + 2][lr] = rb0.z; Bs[nxt][lc + 3][lr] = rb0.w;
                    Bs[nxt][lc + 0][lr + 64] = rb1.x; Bs[nxt][lc + 1][lr + 64] = rb1.y;
                    Bs[nxt][lc + 2][lr + 64] = rb1.z; Bs[nxt][lc + 3][lr + 64] = rb1.w;
                }
                __syncthreads();
            }

            float bv[8];
            #pragma unroll
            for (int j = 0; j < 8; j++) bv[j] = bia[bn + tx * 8 + j];
            #pragma unroll
            for (int i = 0; i < 4; i++) {
                size_t m = m0 + ty * 4 + i;
                float4 o0, o1;
                o0.x = acc[i][0] + bv[0]; o0.y = acc[i][1] + bv[1];
                o0.z = acc[i][2] + bv[2]; o0.w = acc[i][3] + bv[3];
                o1.x = acc[i][4] + bv[4]; o1.y = acc[i][5] + bv[5];
                o1.z = acc[i][6] + bv[6]; o1.w = acc[i][7] + bv[7];
                *(float4*)&g_proj[m * H_ + bn + tx * 8]     = o0;
                *(float4*)&g_proj[m * H_ + bn + tx * 8 + 4] = o1;
            }

            __syncthreads();
            if (tid == 0) {
                __threadfence();
                atomicAdd(&g_flag[b * NCH + tc], 1u);
            }
        }
        return;
    }

    // ======================= scan role (2 batches) =======================
    const int bA = cta;
    const int bB = cta + 16;
    const int h = tid;
    const int wid = tid >> 5, lane = tid & 31;
    const int q = tid >> 6, u = tid & 63;

    const float* pbA = g_proj + (size_t)bA * T_ * H_;
    const float* pbB = g_proj + (size_t)bB * T_ * H_;
    float* obA = out + (size_t)bA * T_ * H_;
    float* obB = out + (size_t)bB * T_ * H_;
    const float brec = b_rec[h];
    const unsigned* fA = g_flag + bA * NCH;
    const unsigned* fB = g_flag + bB * NCH;

    const char* tbase = (const char*)g_tab
                      + ((size_t)q * 8 * NP * H_ * 4)
                      + (size_t)u * 16;

    if (tid < 8) { sbits[0][0][tid] = 0u; sbits[0][1][tid] = 0u; }
    __syncthreads();

    // wait for both batches' first chunk, then seed 2-deep prefetch
    if (tid == 0) wait_chunk(fA);
    else if (tid == 1) wait_chunk(fB);
    __syncthreads();

    float memA = 0.0f, spkA = 0.0f, memB = 0.0f, spkB = 0.0f;
    int buf = 0;
    float pA0 = pbA[h], pA1 = pbA[H_ + h];
    float pB0 = pbB[h], pB1 = pbB[H_ + h];

    for (int t = 0; t < T_; t++) {
        const int tn = t + 2;
        if (tn < T_ && (tn & 63) == 0) {
            if (tid == 0) wait_chunk(fA + (tn >> 6));
            else if (tid == 1) wait_chunk(fB + (tn >> 6));
            __syncthreads();
        }
        float pA2 = 0.0f, pB2 = 0.0f;
        if (tn < T_) {
            pA2 = pbA[(size_t)tn * H_ + h];
            pB2 = pbB[(size_t)tn * H_ + h];
        }

        // ---- phase 1: gathers for both batches (MLP across streams) ----
        const unsigned aw0 = sbits[buf][0][2 * q], aw1 = sbits[buf][0][2 * q + 1];
        const unsigned bw0 = sbits[buf][1][2 * q], bw1 = sbits[buf][1][2 * q + 1];
        float4 accA = gather8(tbase, aw0, aw1);
        float4 accB = gather8(tbase, bw0, bw1);
        sp[buf][0][q][u] = accA;
        sp[buf][1][q][u] = accB;
        __syncthreads();   // A

        // ---- phase 2: combine + LIF for both batches ----
        const int uu = h >> 2, c = h & 3;
        float rA, rB;
        {
            const float r0 = ((const float*)&sp[buf][0][0][uu])[c];
            const float r1 = ((const float*)&sp[buf][0][1][uu])[c];
            const float r2 = ((const float*)&sp[buf][0][2][uu])[c];
            const float r3 = ((const float*)&sp[buf][0][3][uu])[c];
            rA = __fadd_rn(__fadd_rn(__fadd_rn(r0, r1), __fadd_rn(r2, r3)), brec);
        }
        {
            const float r0 = ((const float*)&sp[buf][1][0][uu])[c];
            const float r1 = ((const float*)&sp[buf][1][1][uu])[c];
            const float r2 = ((const float*)&sp[buf][1][2][uu])[c];
            const float r3 = ((const float*)&sp[buf][1][3][uu])[c];
            rB = __fadd_rn(__fadd_rn(__fadd_rn(r0, r1), __fadd_rn(r2, r3)), brec);
        }

        const float resetA = (memA > 1.0f) ? 1.0f : 0.0f;
        const float inA = __fadd_rn(pA0, spkA);
        memA = __fsub_rn(__fadd_rn(__fadd_rn(__fmul_rn(0.85f, memA), inA), rA), resetA);
        const float sA = (memA > 1.0f) ? 1.0f : 0.0f;
        obA[(size_t)t * H_ + h] = sA;

        const float resetB = (memB > 1.0f) ? 1.0f : 0.0f;
        const float inB = __fadd_rn(pB0, spkB);
        memB = __fsub_rn(__fadd_rn(__fadd_rn(__fmul_rn(0.85f, memB), inB), rB), resetB);
        const float sB = (memB > 1.0f) ? 1.0f : 0.0f;
        obB[(size_t)t * H_ + h] = sB;

        const unsigned ballA = __ballot_sync(0xFFFFFFFFu, sA != 0.0f);
        const unsigned ballB = __ballot_sync(0xFFFFFFFFu, sB != 0.0f);
        const int nb = buf ^ 1;
        if (lane == 0) {
            sbits[nb][0][wid] = ballA;
            sbits[nb][1][wid] = ballB;
        }
        __syncthreads();   // B

        buf = nb; spkA = sA; spkB = sB;
        pA0 = pA1; pA1 = pA2;
        pB0 = pB1; pB1 = pB2;
    }
}

// ---------------------------------------------------------------------------
extern "C" void kernel_launch(void* const* d_in, const int* in_sizes, int n_in,
                              void* d_out, int out_size) {
    const float* x     = (const float*)d_in[0];
    const float* W_in  = (const float*)d_in[1];
    const float* b_in  = (const float*)d_in[2];
    const float* V     = (const float*)d_in[3];
    const float* b_rec = (const float*)d_in[4];
    float* out = (float*)d_out;

    transpose_V<<<H_, H_>>>(V);
    build_tab<<<NG * NP, H_>>>();
    init_flags<<<1, B_ * NCH>>>();
    fused_kernel<<<NSCAN + NWORK, 256>>>(x, W_in, b_in, b_rec, out);
}

// round 9
// speedup vs baseline: 1.9502x; 1.9502x over previous
#include <cuda_runtime.h>
#include <cstdint>

#define B_  32
#define T_  2048
#define IN_ 512
#define H_  256
#define NG  32      // groups of 8 presynaptic neurons
#define NP  256     // patterns per group (2^8)
#define NCH 32      // T_/64 proj chunks per batch

#define NSCAN 32    // scan CTAs (one per batch)
#define NWORK 116   // persistent GEMM worker CTAs
#define NJOBS 2048  // (B_*T_/GM) * 2 n-halves

// Scratch (allocation-free rule: __device__ globals)
__device__ float g_proj[(size_t)B_ * T_ * H_];        // 64 MB input projection
__device__ float g_Vt[H_ * H_];                       // Vt[j][h] = V[h][j]
__device__ float g_tab[(size_t)NG * NP * H_];         // 8 MB group subset-sum table
__device__ unsigned g_flag[B_ * NCH];                 // producer->consumer chunk flags

// ---------------------------------------------------------------------------
// Setup kernels
// ---------------------------------------------------------------------------
__global__ void transpose_V(const float* __restrict__ V) {
    int j = blockIdx.x;
    int h = threadIdx.x;
    g_Vt[j * H_ + h] = V[h * H_ + j];
}

// tab[g][p][h] = sum_{i: bit i of p} Vt[8g+i][h]   (ascending i)
__global__ void build_tab(void) {
    const int blk = blockIdx.x;          // 0..8191
    const int g = blk >> 8;
    const int p = blk & 255;
    const int h = threadIdx.x;
    float s = 0.0f;
    #pragma unroll
    for (int i = 0; i < 8; i++)
        if ((p >> i) & 1)
            s = __fadd_rn(s, g_Vt[(g * 8 + i) * H_ + h]);
    g_tab[((size_t)g * NP + p) * H_ + h] = s;
}

__global__ void init_flags(void) {
    g_flag[threadIdx.x] = 0u;
}

// ---------------------------------------------------------------------------
// chunk-ready spin (acquire)
// ---------------------------------------------------------------------------
__device__ __forceinline__ void wait_chunk(const unsigned* f) {
    unsigned v;
    do {
        asm volatile("ld.acquire.gpu.global.u32 %0, [%1];"
                     : "=r"(v) : "l"(f) : "memory");
    } while (v < 2u);
}

// ---------------------------------------------------------------------------
// Fused persistent kernel.
//   CTA 0..31   : LIF scan for batch = blockIdx.x (single-barrier scheme)
//   CTA 32..147 : GEMM workers, grid-stride over NJOBS tile jobs
// ---------------------------------------------------------------------------
#define GM 64
#define GN 128
#define GK 16

__global__ __launch_bounds__(256, 1) void fused_kernel(
    const float* __restrict__ x, const float* __restrict__ W,
    const float* __restrict__ bia,
    const float* __restrict__ b_rec, float* __restrict__ out) {

    __shared__ float As[2][GK][GM];       // GEMM buffers (worker role)
    __shared__ float Bs[2][GK][GN];
    __shared__ uint4 sbits[2][2];         // [buf][half]: 8 ballot words

    const int cta = blockIdx.x;
    const int tid = threadIdx.x;

    if (cta >= NSCAN) {
        // =================== GEMM worker role (R7-identical) ===================
        const int tx = tid & 15;
        const int ty = tid >> 4;
        const int lr = tid >> 2;
        const int lc = (tid & 3) * 4;

        for (int jj = cta - NSCAN; jj < NJOBS; jj += NWORK) {
            const int nt = jj & 1;
            const int b  = (jj >> 1) & 31;
            const int tc = jj >> 6;
            const size_t m0 = (size_t)b * T_ + (size_t)tc * GM;
            const int bn = nt * GN;

            float acc[4][8];
            #pragma unroll
            for (int i = 0; i < 4; i++)
                #pragma unroll
                for (int j = 0; j < 8; j++) acc[i][j] = 0.0f;

            float4 ra, rb0, rb1;
            ra  = *(const float4*)&x[(m0 + lr) * IN_ + lc];
            rb0 = *(const float4*)&W[(size_t)(bn + lr) * IN_ + lc];
            rb1 = *(const float4*)&W[(size_t)(bn + 64 + lr) * IN_ + lc];
            As[0][lc + 0][lr] = ra.x;  As[0][lc + 1][lr] = ra.y;
            As[0][lc + 2][lr] = ra.z;  As[0][lc + 3][lr] = ra.w;
            Bs[0][lc + 0][lr] = rb0.x; Bs[0][lc + 1][lr] = rb0.y;
            Bs[0][lc + 2][lr] = rb0.z; Bs[0][lc + 3][lr] = rb0.w;
            Bs[0][lc + 0][lr + 64] = rb1.x; Bs[0][lc + 1][lr + 64] = rb1.y;
            Bs[0][lc + 2][lr + 64] = rb1.z; Bs[0][lc + 3][lr + 64] = rb1.w;
            __syncthreads();

            const int NT = IN_ / GK;   // 32
            for (int kt = 0; kt < NT; kt++) {
                const int cur = kt & 1, nxt = cur ^ 1;
                if (kt + 1 < NT) {
                    int k0 = (kt + 1) * GK + lc;
                    ra  = *(const float4*)&x[(m0 + lr) * IN_ + k0];
                    rb0 = *(const float4*)&W[(size_t)(bn + lr) * IN_ + k0];
                    rb1 = *(const float4*)&W[(size_t)(bn + 64 + lr) * IN_ + k0];
                }
                #pragma unroll
                for (int kk = 0; kk < GK; kk++) {
                    float a[4], bb[8];
                    *(float4*)&a[0]  = *(const float4*)&As[cur][kk][ty * 4];
                    *(float4*)&bb[0] = *(const float4*)&Bs[cur][kk][tx * 8];
                    *(float4*)&bb[4] = *(const float4*)&Bs[cur][kk][tx * 8 + 4];
                    #pragma unroll
                    for (int i = 0; i < 4; i++)
                        #pragma unroll
                        for (int j = 0; j < 8; j++)
                            acc[i][j] = fmaf(a[i], bb[j], acc[i][j]);
                }
                if (kt + 1 < NT) {
                    As[nxt][lc + 0][lr] = ra.x;  As[nxt][lc + 1][lr] = ra.y;
                    As[nxt][lc + 2][lr] = ra.z;  As[nxt][lc + 3][lr] = ra.w;
                    Bs[nxt][lc + 0][lr] = rb0.x; Bs[nxt][lc + 1][lr] = rb0.y;
                    Bs[nxt][lc + 2][lr] = rb0.z; Bs[nxt][lc + 3][lr] = rb0.w;
                    Bs[nxt][lc + 0][lr + 64] = rb1.x; Bs[nxt][lc + 1][lr + 64] = rb1.y;
                    Bs[nxt][lc + 2][lr + 64] = rb1.z; Bs[nxt][lc + 3][lr + 64] = rb1.w;
                }
                __syncthreads();
            }

            float bv[8];
            #pragma unroll
            for (int j = 0; j < 8; j++) bv[j] = bia[bn + tx * 8 + j];
            #pragma unroll
            for (int i = 0; i < 4; i++) {
                size_t m = m0 + ty * 4 + i;
                float4 o0, o1;
                o0.x = acc[i][0] + bv[0]; o0.y = acc[i][1] + bv[1];
                o0.z = acc[i][2] + bv[2]; o0.w = acc[i][3] + bv[3];
                o1.x = acc[i][4] + bv[4]; o1.y = acc[i][5] + bv[5];
                o1.z = acc[i][6] + bv[6]; o1.w = acc[i][7] + bv[7];
                *(float4*)&g_proj[m * H_ + bn + tx * 8]     = o0;
                *(float4*)&g_proj[m * H_ + bn + tx * 8 + 4] = o1;
            }

            __syncthreads();
            if (tid == 0) {
                __threadfence();
                atomicAdd(&g_flag[b * NCH + tc], 1u);
            }
        }
        return;
    }

    // ======================= scan role (single barrier/step) =======================
    // Warp w owns neurons [32w, 32w+32); lane l = neuron h = 32w+l computes its
    // own 32-group sum with scalar loads: group g -> tab[(g*256+pat_g)*256 + h].
    // Per group-load the warp touches 128 consecutive bytes = 1 L1 wavefront.
    const int b = cta;
    const int h = tid;
    const int w = tid >> 5, lane = tid & 31;

    const float* pb = g_proj + (size_t)b * T_ * H_;
    float* ob = out + (size_t)b * T_ * H_;
    const float brec = b_rec[h];
    const unsigned* fb = g_flag + b * NCH;
    const float* tb = g_tab + h;          // column h, row stride 256 floats

    if (tid == 0) {
        sbits[0][0] = make_uint4(0u, 0u, 0u, 0u);
        sbits[0][1] = make_uint4(0u, 0u, 0u, 0u);
    }
    __syncthreads();

    if (tid == 0) wait_chunk(fb);
    __syncthreads();

    float mem = 0.0f, spk = 0.0f;
    int buf = 0;
    float p0 = pb[h];
    float p1 = pb[H_ + h];

    for (int t = 0; t < T_; t++) {
        const int tn = t + 2;
        if (tn < T_ && (tn & 63) == 0) {
            if (tid == 0) wait_chunk(fb + (tn >> 6));
            __syncthreads();
        }
        float p2 = (tn < T_) ? pb[(size_t)tn * H_ + h] : 0.0f;

        // ---- read the 8 ballot words (broadcast LDS.128 x2) ----
        const uint4 u0 = sbits[buf][0];
        const uint4 u1 = sbits[buf][1];
        const unsigned wd[8] = {u0.x, u0.y, u0.z, u0.w, u1.x, u1.y, u1.z, u1.w};

        // ---- 32 group-row loads; accumulator tree identical to R4/R7 ----
        float acck[4];
        #pragma unroll
        for (int k = 0; k < 4; k++) {
            float a = 0.0f;
            #pragma unroll
            for (int gg = 0; gg < 8; gg++) {
                const int g = k * 8 + gg;
                const unsigned pat = (wd[g >> 2] >> ((g & 3) * 8)) & 0xFFu;
                a = __fadd_rn(a, __ldg(&tb[(unsigned)((g << 8) | (int)pat) << 8]));
            }
            acck[k] = a;
        }
        float rec = __fadd_rn(__fadd_rn(acck[0], acck[1]),
                              __fadd_rn(acck[2], acck[3]));
        rec = __fadd_rn(rec, brec);

        // ---- LIF update (bitwise-identical rounding order) ----
        const float reset = (mem > 1.0f) ? 1.0f : 0.0f;
        const float in_ = __fadd_rn(p0, spk);
        mem = __fsub_rn(__fadd_rn(__fadd_rn(__fmul_rn(0.85f, mem), in_), rec), reset);
        const float s = (mem > 1.0f) ? 1.0f : 0.0f;
        ob[(size_t)t * H_ + h] = s;

        // ---- publish spikes; single barrier per step ----
        const unsigned ball = __ballot_sync(0xFFFFFFFFu, s != 0.0f);
        const int nb = buf ^ 1;
        if (lane == 0) ((unsigned*)&sbits[nb][0])[w] = ball;
        __syncthreads();

        buf = nb; spk = s;
        p0 = p1; p1 = p2;
    }
}

// ---------------------------------------------------------------------------
extern "C" void kernel_launch(void* const* d_in, const int* in_sizes, int n_in,
                              void* d_out, int out_size) {
    const float* x     = (const float*)d_in[0];
    const float* W_in  = (const float*)d_in[1];
    const float* b_in  = (const float*)d_in[2];
    const float* V     = (const float*)d_in[3];
    const float* b_rec = (const float*)d_in[4];
    float* out = (float*)d_out;

    transpose_V<<<H_, H_>>>(V);
    build_tab<<<NG * NP, H_>>>();
    init_flags<<<1, B_ * NCH>>>();
    fused_kernel<<<NSCAN + NWORK, 256>>>(x, W_in, b_in, b_rec, out);
}